// round 10
// baseline (speedup 1.0000x reference)
#include <cuda_runtime.h>
#include <cstdint>

// NodePropagatorSparse: out[b,e,0:256]   = node_states[b, edge_src[e], :]
//                       out[b,e,256:512] = node_states[b, edge_tgt[e], :]
// B=4, N=10000, E=160000, D=256. node_states fp32, indices int32 (JAX x64-off).
//
// R9: batch phasing (blockIdx.y=b -> 10.24MB L2-resident gather set/phase)
// + edge-unroll x4 (MLP=4) + Blackwell 256-bit LDG/STG (.v8.f32): half the
// LSU instructions, 32B/lane contiguous bursts. Streaming (.cs) stores.

#define B_DIM 4
#define N_DIM 10000
#define E_DIM 160000
#define D_DIM 256
#define D8    (D_DIM / 8)        // 32 x 32B chunks per D-row
#define ROW8  (2 * D8)           // 64 x 32B chunks per output (b,e) row
#define EDGES_PER_BLOCK 16
#define UNROLL 4

struct V32 { float x0,x1,x2,x3,x4,x5,x6,x7; };   // 32 bytes

__device__ __forceinline__ V32 ldg256(const V32* p) {
    V32 v;
    asm volatile("ld.global.v8.f32 {%0,%1,%2,%3,%4,%5,%6,%7}, [%8];"
                 : "=f"(v.x0), "=f"(v.x1), "=f"(v.x2), "=f"(v.x3),
                   "=f"(v.x4), "=f"(v.x5), "=f"(v.x6), "=f"(v.x7)
                 : "l"(p));
    return v;
}

__device__ __forceinline__ void stcs256(V32* p, const V32& v) {
    asm volatile("st.global.cs.v8.f32 [%0], {%1,%2,%3,%4,%5,%6,%7,%8};"
                 :: "l"(p),
                    "f"(v.x0), "f"(v.x1), "f"(v.x2), "f"(v.x3),
                    "f"(v.x4), "f"(v.x5), "f"(v.x6), "f"(v.x7)
                 : "memory");
}

__global__ __launch_bounds__(256, 8)
void node_prop_gather_kernel(const V32* __restrict__ ns,    // [B, N, D8]
                             const int* __restrict__ src,   // [E] int32
                             const int* __restrict__ tgt,   // [E] int32
                             V32* __restrict__ out)         // [B, E, ROW8]
{
    const int t    = threadIdx.x;                 // 0..255
    const int b    = blockIdx.y;                  // batch phase
    const int col  = t & 31;                      // 32B column within D-row
    const int half = (t >> 5) & 1;                // 0 = src half, 1 = tgt half
    const int esub = t >> 6;                      // 0..3: edge within group

    const int e0 = blockIdx.x * EDGES_PER_BLOCK + esub;
    const int* iarr = half ? tgt : src;

    const V32* nsb = ns + (size_t)b * ((size_t)N_DIM * D8) + col;
    V32* outb = out + (size_t)b * ((size_t)E_DIM * ROW8) + half * D8 + col;

    int idx[UNROLL];
#pragma unroll
    for (int u = 0; u < UNROLL; u++)
        idx[u] = iarr[e0 + 4 * u];

    V32 v[UNROLL];
#pragma unroll
    for (int u = 0; u < UNROLL; u++)
        v[u] = ldg256(nsb + (size_t)idx[u] * D8);

#pragma unroll
    for (int u = 0; u < UNROLL; u++)
        stcs256(outb + (size_t)(e0 + 4 * u) * ROW8, v[u]);
}

extern "C" void kernel_launch(void* const* d_in, const int* in_sizes, int n_in,
                              void* d_out, int out_size)
{
    const V32* ns   = (const V32*)d_in[0];
    const int* src  = (const int*)d_in[1];
    const int* tgt  = (const int*)d_in[2];
    V32*       out  = (V32*)d_out;

    dim3 grid(E_DIM / EDGES_PER_BLOCK, B_DIM);   // (10000, 4)
    node_prop_gather_kernel<<<grid, 256>>>(ns, src, tgt, out);
}

// round 11
// speedup vs baseline: 1.2083x; 1.2083x over previous
#include <cuda_runtime.h>
#include <cstdint>

// NodePropagatorSparse: out[b,e,0:256]   = node_states[b, edge_src[e], :]
//                       out[b,e,256:512] = node_states[b, edge_tgt[e], :]
// B=4, N=10000, E=160000, D=256. node_states fp32, indices int32 (JAX x64-off).
//
// R11 (= R7 revert + micro-opts): batch phasing via blockIdx.y keeps the
// per-phase gather set at 10.24MB (L2-resident; this removed all excess DRAM
// reads), edge-unroll x4 gives MLP=4 (saturates write drain), float4 128-bit
// ops (R9 showed 256-bit regresses), __stcs evict-first streaming stores
// (R3 win). 32-bit offset arithmetic; all offsets fit in int.

#define B_DIM 4
#define N_DIM 10000
#define E_DIM 160000
#define D_DIM 256
#define D4    (D_DIM / 4)        // 64 float4 per D-row
#define ROW4  (2 * D4)           // 128 float4 per output (b,e) row
#define EDGES_PER_BLOCK 8
#define UNROLL 4

__global__ __launch_bounds__(256, 8)
void node_prop_gather_kernel(const float4* __restrict__ ns4,   // [B, N, D4]
                             const int* __restrict__ src,      // [E] int32
                             const int* __restrict__ tgt,      // [E] int32
                             float4* __restrict__ out4)        // [B, E, ROW4]
{
    const int t    = threadIdx.x;                 // 0..255
    const int b    = blockIdx.y;                  // batch phase
    const int half = (t >> 6) & 1;                // 0 = src half, 1 = tgt half
    const int col  = t & 63;                      // float4 column within D-row
    const int esub = t >> 7;                      // 0..1: edge-within-pair

    const int e0 = blockIdx.x * EDGES_PER_BLOCK + esub;
    const int* iarr = half ? tgt : src;

    // 32-bit offsets: max ns offset = 4*10000*64 = 2.56M, max out offset =
    // 4*160000*128 = 81.92M float4 -> both fit comfortably in int.
    const float4* nsb  = ns4  + (b * N_DIM) * D4 + col;
    float4*       outb = out4 + (b * E_DIM + e0) * ROW4 + half * D4 + col;

    int idx[UNROLL];
#pragma unroll
    for (int u = 0; u < UNROLL; u++)
        idx[u] = __ldg(&iarr[e0 + 2 * u]);

    float4 v[UNROLL];
#pragma unroll
    for (int u = 0; u < UNROLL; u++)
        v[u] = nsb[idx[u] * D4];

#pragma unroll
    for (int u = 0; u < UNROLL; u++)
        __stcs(outb + (2 * u) * ROW4, v[u]);
}

extern "C" void kernel_launch(void* const* d_in, const int* in_sizes, int n_in,
                              void* d_out, int out_size)
{
    const float4* ns4  = (const float4*)d_in[0];
    const int*    src  = (const int*)d_in[1];
    const int*    tgt  = (const int*)d_in[2];
    float4*       out4 = (float4*)d_out;

    dim3 grid(E_DIM / EDGES_PER_BLOCK, B_DIM);   // (20000, 4)
    node_prop_gather_kernel<<<grid, 256>>>(ns4, src, tgt, out4);
}